// round 5
// baseline (speedup 1.0000x reference)
#include <cuda_runtime.h>

#define Bb 2
#define Nn 512
#define Ff 16
#define Dd 64
#define Hh 4
#define DhD 16
#define Cc 4
#define HIDD 256
#define NEGV (-9.0e15f)
#define MAXD 96
#define BPR 8          // rows per block in k1/k2

// scratch (allocation-free rule: __device__ globals)
__device__ __align__(16) float g_h[Bb*Nn*Dd];
__device__ __align__(16) float g_q[Bb*Hh*Nn*DhD];
__device__ __align__(16) float g_k[Bb*Hh*Nn*DhD];
__device__ __align__(16) float g_v[Bb*Hh*Nn*DhD];
__device__ __align__(16) float g_a[Bb*Nn*HIDD];   // y@W1[:D] + b1
__device__ __align__(16) float g_bb[Bb*Nn*HIDD];  // y@W1[D:]
__device__ int g_cnt[Nn];
__device__ int g_js[Nn*MAXD];

// ---------------------------------------------------------------------------
// K1: 8 rows per block, 128 blocks x 256 threads.
//   - NEG fill of the 8 rows' output (overlaps stalls)
//   - h = x @ W_emb for 8 rows (thread = (r,c) item)
//   - q/k/v: warps 0..5 = (matrix, col-half); thread = col, loop d, 8-row FMA
//     -> each weight element loaded ONCE per block (8x traffic cut)
//   - warps 6,7: adjacency compaction (b==0 blocks), overlapped
// ---------------------------------------------------------------------------
__global__ void k1_embed_qkv(const float* __restrict__ x,
                             const float* __restrict__ adj,
                             const float* __restrict__ W_emb,
                             const float* __restrict__ Wq,
                             const float* __restrict__ Wk,
                             const float* __restrict__ Wv,
                             float* __restrict__ out) {
    __shared__ float xsh[BPR][Ff];
    __shared__ float hsh[BPR][Dd];
    const int t = threadIdx.x;
    const int warp = t >> 5, lane = t & 31;
    const int row0 = blockIdx.x * BPR;
    const int b = row0 >> 9, n0 = row0 & (Nn - 1);

    // ---- NEG fill: 8 rows x 4 ch x 512 floats = 4096 float4, 16/thread ----
    {
        const float4 neg4 = make_float4(NEGV, NEGV, NEGV, NEGV);
#pragma unroll
        for (int s = 0; s < 16; s++) {
            const int e = s * 256 + t;
            const int r = e >> 9;
            const int rem = e & 511;
            const int ch = rem >> 7, col4 = rem & 127;
            float4* rp = (float4*)(out + (((size_t)(b * Cc + ch) * Nn + (n0 + r)) * Nn));
            rp[col4] = neg4;
        }
    }

    // ---- stage x ----
    if (t < BPR * Ff) xsh[t >> 4][t & 15] = x[row0 * Ff + t];
    __syncthreads();

    // ---- h for 8 rows: 512 items, 2 per thread ----
#pragma unroll
    for (int s = 0; s < 2; s++) {
        const int e = t + s * 256;
        const int r = e >> 6, c = e & 63;
        float acc = 0.f;
#pragma unroll
        for (int f = 0; f < Ff; f++)
            acc += xsh[r][f] * __ldg(W_emb + f * Dd + c);
        hsh[r][c] = acc;
        g_h[(row0 + r) * Dd + c] = acc;
    }
    __syncthreads();

    // ---- qkv (warps 0..5) / adjacency (warps 6,7) ----
    if (t < 192) {
        const int m = t >> 6;       // 0=q,1=k,2=v (warp-uniform)
        const int c = t & 63;
        const float* W = (m == 0) ? Wq : ((m == 1) ? Wk : Wv);
        float acc[BPR];
#pragma unroll
        for (int r = 0; r < BPR; r++) acc[r] = 0.f;
#pragma unroll 8
        for (int d = 0; d < Dd; d++) {
            const float w = __ldg(W + d * Dd + c);
#pragma unroll
            for (int r = 0; r < BPR; r++) acc[r] += hsh[r][d] * w;
        }
        const int hd = c >> 4, dh = c & 15;
        float* G = (m == 0) ? g_q : ((m == 1) ? g_k : g_v);
#pragma unroll
        for (int r = 0; r < BPR; r++)
            G[((b * Hh + hd) * Nn + (n0 + r)) * DhD + dh] = acc[r];
    } else if (b == 0) {
        const int w8 = warp - 6;    // 0 or 1
        for (int rr = 0; rr < 4; rr++) {
            const int r = row0 + w8 * 4 + rr;
            const float* arow = adj + r * Nn;
            int base = 0;
#pragma unroll
            for (int tt = 0; tt < 16; tt++) {
                const int j = tt * 32 + lane;
                const bool hit = (arow[j] > 0.f);
                const unsigned bal = __ballot_sync(0xffffffffu, hit);
                if (hit) {
                    const int pos = base + __popc(bal & ((1u << lane) - 1u));
                    if (pos < MAXD) g_js[r * MAXD + pos] = j;
                }
                base += __popc(bal);
            }
            if (lane == 0) g_cnt[r] = (base < MAXD) ? base : MAXD;
        }
    }
}

// ---------------------------------------------------------------------------
// K2: 8 rows per block, 128 blocks x 256 threads.
//   - attention: warp = local row, loop over 4 heads (sparse neighbor list)
//   - y = h + o@Wo : thread = (r,c)x2 sharing the same Wo column loads
//   - a/b = y@W1 halves: thread = column (256), loop d, 8-row FMA
//     -> W1 read ONCE per block: 128MB -> 16MB L2 traffic
// ---------------------------------------------------------------------------
__global__ void k2_attn_ff(const float* __restrict__ Wo,
                           const float* __restrict__ W1,
                           const float* __restrict__ b1) {
    __shared__ float osh[BPR][Dd];
    __shared__ float ysh[BPR][Dd];
    const int t = threadIdx.x;
    const int warp = t >> 5, lane = t & 31;
    const int row0 = blockIdx.x * BPR;
    const int b = row0 >> 9, n0 = row0 & (Nn - 1);

    // ---- attention: warp = local row r, loop heads ----
    {
        const int r = warp;
        const int i = n0 + r;
        const int cnt = g_cnt[i];
        const int* js = g_js + i * MAXD;
        const int nch = (cnt + 31) >> 5;   // <= 3

        for (int hd = 0; hd < Hh; hd++) {
            const float* qrow = g_q + ((b * Hh + hd) * Nn + i) * DhD;
            float qr[DhD];
#pragma unroll
            for (int d = 0; d < DhD; d++) qr[d] = __ldg(qrow + d);

            const float* kbase = g_k + (b * Hh + hd) * Nn * DhD;
            const float* vbase = g_v + (b * Hh + hd) * Nn * DhD;

            float sc[3];
            int jj[3];
            float m = -3.0e38f;
#pragma unroll
            for (int c = 0; c < 3; c++) {
                sc[c] = -3.0e38f; jj[c] = 0;
                if (c < nch) {
                    const int e = c * 32 + lane;
                    if (e < cnt) {
                        const int j = js[e];
                        jj[c] = j;
                        const float* kr = kbase + j * DhD;
                        float dot = 0.f;
#pragma unroll
                        for (int d = 0; d < DhD; d++) dot += qr[d] * kr[d];
                        sc[c] = dot * 0.25f;
                    }
                    m = fmaxf(m, sc[c]);
                }
            }
#pragma unroll
            for (int o = 16; o > 0; o >>= 1)
                m = fmaxf(m, __shfl_xor_sync(0xffffffffu, m, o));

            float sum = 0.f;
#pragma unroll
            for (int c = 0; c < 3; c++) {
                sc[c] = expf(sc[c] - m);
                sum += sc[c];
            }
#pragma unroll
            for (int o = 16; o > 0; o >>= 1)
                sum += __shfl_xor_sync(0xffffffffu, sum, o);

            float ov[DhD];
#pragma unroll
            for (int d = 0; d < DhD; d++) ov[d] = 0.f;
#pragma unroll
            for (int c = 0; c < 3; c++) {
                if (c < nch && sc[c] > 0.f) {
                    const float* vr = vbase + jj[c] * DhD;
                    const float e = sc[c];
#pragma unroll
                    for (int d = 0; d < DhD; d++) ov[d] += e * vr[d];
                }
            }
#pragma unroll
            for (int d = 0; d < DhD; d++) {
#pragma unroll
                for (int o = 16; o > 0; o >>= 1)
                    ov[d] += __shfl_xor_sync(0xffffffffu, ov[d], o);
            }
            if (lane == 0) {
                const float inv = 1.f / sum;
#pragma unroll
                for (int d = 0; d < DhD; d++) osh[r][hd * DhD + d] = ov[d] * inv;
            }
        }
    }
    __syncthreads();

    // ---- y = h + o @ Wo : thread covers (rA,c) and (rA+4,c), shared w ----
    {
        const int c = t & 63;
        const int rA = t >> 6, rB = rA + 4;
        float accA = g_h[(row0 + rA) * Dd + c];
        float accB = g_h[(row0 + rB) * Dd + c];
#pragma unroll 8
        for (int e = 0; e < Dd; e++) {
            const float w = __ldg(Wo + e * Dd + c);
            accA += osh[rA][e] * w;
            accB += osh[rB][e] * w;
        }
        ysh[rA][c] = accA;
        ysh[rB][c] = accB;
    }
    __syncthreads();

    // ---- a/b: thread = column c in [0,256), loop d, 8 rows ----
    {
        const int c = t;
        const float bias = __ldg(b1 + c);
        float fa[BPR], fb[BPR];
#pragma unroll
        for (int r = 0; r < BPR; r++) { fa[r] = 0.f; fb[r] = 0.f; }
#pragma unroll 4
        for (int d = 0; d < Dd; d++) {
            const float wa = __ldg(W1 + d * HIDD + c);
            const float wb = __ldg(W1 + (Dd + d) * HIDD + c);
#pragma unroll
            for (int r = 0; r < BPR; r++) {
                const float yv = ysh[r][d];
                fa[r] += yv * wa;
                fb[r] += yv * wb;
            }
        }
#pragma unroll
        for (int r = 0; r < BPR; r++) {
            g_a [(row0 + r) * HIDD + c] = fa[r] + bias;
            g_bb[(row0 + r) * HIDD + c] = fb[r];
        }
    }
}

// ---------------------------------------------------------------------------
// K3: sparse scatter only. grid = B*N blocks of 128.
// ---------------------------------------------------------------------------
__global__ void k3_out(const float* __restrict__ W2,
                       const float* __restrict__ b2,
                       float* __restrict__ out) {
    const int row = blockIdx.x;
    const int b = row >> 9, i = row & (Nn - 1);
    const int warp = threadIdx.x >> 5;
    const int lane = threadIdx.x & 31;

    const int cnt = g_cnt[i];
    const int* js = g_js + i * MAXD;
    const int h0 = lane * 8;

    const float4* ap = (const float4*)(g_a + row * HIDD + h0);
    const float4 a0 = ap[0], a1 = ap[1];
    float4 w[8];
#pragma unroll
    for (int k = 0; k < 8; k++) w[k] = __ldg((const float4*)W2 + h0 + k);
    const float b20 = __ldg(b2 + 0), b21 = __ldg(b2 + 1);
    const float b22 = __ldg(b2 + 2), b23 = __ldg(b2 + 3);

    for (int e = warp; e < cnt; e += 4) {
        const int j = js[e];
        const float4* bp = (const float4*)(g_bb + ((size_t)(b * Nn + j)) * HIDD + h0);
        const float4 bv0 = bp[0], bv1 = bp[1];

        float acc0 = 0.f, acc1 = 0.f, acc2 = 0.f, acc3 = 0.f;
        float t;
#define RELU_FMA(AV, BV, WK) \
        t = fmaxf((AV) + (BV), 0.f); \
        acc0 += t * (WK).x; acc1 += t * (WK).y; acc2 += t * (WK).z; acc3 += t * (WK).w;
        RELU_FMA(a0.x, bv0.x, w[0]);
        RELU_FMA(a0.y, bv0.y, w[1]);
        RELU_FMA(a0.z, bv0.z, w[2]);
        RELU_FMA(a0.w, bv0.w, w[3]);
        RELU_FMA(a1.x, bv1.x, w[4]);
        RELU_FMA(a1.y, bv1.y, w[5]);
        RELU_FMA(a1.z, bv1.z, w[6]);
        RELU_FMA(a1.w, bv1.w, w[7]);
#undef RELU_FMA

#pragma unroll
        for (int o = 16; o > 0; o >>= 1) {
            acc0 += __shfl_xor_sync(0xffffffffu, acc0, o);
            acc1 += __shfl_xor_sync(0xffffffffu, acc1, o);
            acc2 += __shfl_xor_sync(0xffffffffu, acc2, o);
            acc3 += __shfl_xor_sync(0xffffffffu, acc3, o);
        }
        if (lane == 0) {
            out[(((size_t)(b * Cc + 0) * Nn + i) * Nn) + j] = acc0 + b20;
            out[(((size_t)(b * Cc + 1) * Nn + i) * Nn) + j] = acc1 + b21;
            out[(((size_t)(b * Cc + 2) * Nn + i) * Nn) + j] = acc2 + b22;
            out[(((size_t)(b * Cc + 3) * Nn + i) * Nn) + j] = acc3 + b23;
        }
    }
}

// ---------------------------------------------------------------------------
extern "C" void kernel_launch(void* const* d_in, const int* in_sizes, int n_in,
                              void* d_out, int out_size) {
    const float* x     = (const float*)d_in[0];
    const float* adj   = (const float*)d_in[1];
    const float* W_emb = (const float*)d_in[2];
    const float* Wq    = (const float*)d_in[3];
    const float* Wk    = (const float*)d_in[4];
    const float* Wv    = (const float*)d_in[5];
    const float* Wo    = (const float*)d_in[6];
    const float* W1    = (const float*)d_in[7];
    const float* b1    = (const float*)d_in[8];
    const float* W2    = (const float*)d_in[9];
    const float* b2    = (const float*)d_in[10];
    float* out = (float*)d_out;

    k1_embed_qkv<<<(Bb * Nn) / BPR, 256>>>(x, adj, W_emb, Wq, Wk, Wv, out);
    k2_attn_ff<<<(Bb * Nn) / BPR, 256>>>(Wo, W1, b1);
    k3_out<<<Bb * Nn, 128>>>(W2, b2, out);
}

// round 6
// speedup vs baseline: 1.3825x; 1.3825x over previous
#include <cuda_runtime.h>

#define Bb 2
#define Nn 512
#define Ff 16
#define Dd 64
#define Hh 4
#define DhD 16
#define Cc 4
#define HIDD 256
#define NEGV (-9.0e15f)
#define MAXD 96
#define K2R 4          // rows per block in k2

// scratch (allocation-free rule: __device__ globals)
__device__ __align__(16) float g_h[Bb*Nn*Dd];
__device__ __align__(16) float g_q[Bb*Hh*Nn*DhD];
__device__ __align__(16) float g_k[Bb*Hh*Nn*DhD];
__device__ __align__(16) float g_v[Bb*Hh*Nn*DhD];
__device__ __align__(16) float g_a[Bb*Nn*HIDD];   // y@W1[:D] + b1
__device__ __align__(16) float g_bb[Bb*Nn*HIDD];  // y@W1[D:]
__device__ int g_cnt[Nn];
__device__ int g_js[Nn*MAXD];

// ---------------------------------------------------------------------------
// K1: one block per row (b,n), 256 threads (R4 structure, measured 9.5us).
//   - NEG-fill of this row's 4 output rows (overlaps latency stalls)
//   - h = x @ W_emb (threads 0..63)
//   - q/k/v: float4 weight rows, 16-way segment split, smem reduce
//   - blocks 0..511: warp 0 builds compact adjacency list
// ---------------------------------------------------------------------------
__global__ void k1_embed_qkv(const float* __restrict__ x,
                             const float* __restrict__ adj,
                             const float* __restrict__ W_emb,
                             const float* __restrict__ Wq,
                             const float* __restrict__ Wk,
                             const float* __restrict__ Wv,
                             float* __restrict__ out) {
    __shared__ float hsh[Dd];
    __shared__ float psh[3][16][Dd];
    const int t = threadIdx.x;
    const int row = blockIdx.x;            // b*N + n
    const int b = row >> 9, n = row & (Nn - 1);

    // ---- NEG fill: 4 output rows of 512 floats = 512 float4; 2 per thread
    {
        const float4 neg4 = make_float4(NEGV, NEGV, NEGV, NEGV);
#pragma unroll
        for (int s = 0; s < 2; s++) {
            const int e = s * 256 + t;          // 0..511
            const int c = e >> 7;               // channel
            const int col4 = e & 127;
            float4* rp = (float4*)(out + (((size_t)(b * Cc + c) * Nn + n) * Nn));
            rp[col4] = neg4;
        }
    }

    // ---- phase 1: h = x @ W_emb (threads 0..63) ----
    if (t < Dd) {
        const float* xr = x + row * Ff;
        float acc = 0.f;
#pragma unroll
        for (int f = 0; f < Ff; f++)
            acc += __ldg(xr + f) * __ldg(W_emb + f * Dd + t);
        hsh[t] = acc;
        g_h[row * Dd + t] = acc;
    }
    __syncthreads();

    // ---- phase 2: q/k/v, float4 columns, 16 segs x 4 d's ----
    {
        const int c4 = t & 15;
        const int seg = t >> 4;
        float4 aq = make_float4(0.f, 0.f, 0.f, 0.f);
        float4 ak = aq, av = aq;
#pragma unroll
        for (int dd = 0; dd < 4; dd++) {
            const int d = seg * 4 + dd;
            const float hv = hsh[d];
            const float4 wq = __ldg((const float4*)(Wq + d * Dd) + c4);
            const float4 wk = __ldg((const float4*)(Wk + d * Dd) + c4);
            const float4 wv = __ldg((const float4*)(Wv + d * Dd) + c4);
            aq.x += hv * wq.x; aq.y += hv * wq.y; aq.z += hv * wq.z; aq.w += hv * wq.w;
            ak.x += hv * wk.x; ak.y += hv * wk.y; ak.z += hv * wk.z; ak.w += hv * wk.w;
            av.x += hv * wv.x; av.y += hv * wv.y; av.z += hv * wv.z; av.w += hv * wv.w;
        }
        *(float4*)&psh[0][seg][c4 * 4] = aq;
        *(float4*)&psh[1][seg][c4 * 4] = ak;
        *(float4*)&psh[2][seg][c4 * 4] = av;
    }
    __syncthreads();

    if (t < 192) {
        const int m = t >> 6;       // 0=q,1=k,2=v
        const int c = t & 63;
        float s = 0.f;
#pragma unroll
        for (int seg = 0; seg < 16; seg++) s += psh[m][seg][c];
        const int hd = c >> 4, dh = c & 15;
        const int idx = ((b * Hh + hd) * Nn + n) * DhD + dh;
        if (m == 0) g_q[idx] = s;
        else if (m == 1) g_k[idx] = s;
        else g_v[idx] = s;
    }

    // ---- adjacency compaction: blocks 0..511, warp 0 ----
    if (row < Nn && t < 32) {
        const float* arow = adj + row * Nn;
        int base = 0;
#pragma unroll
        for (int tt = 0; tt < 16; tt++) {
            const int j = tt * 32 + t;
            const bool hit = (arow[j] > 0.f);
            const unsigned bal = __ballot_sync(0xffffffffu, hit);
            if (hit) {
                const int pos = base + __popc(bal & ((1u << t) - 1u));
                if (pos < MAXD) g_js[row * MAXD + pos] = j;
            }
            base += __popc(bal);
        }
        if (t == 0) g_cnt[row] = (base < MAXD) ? base : MAXD;
    }
}

// ---------------------------------------------------------------------------
// K2: 4 rows per block, 256 blocks x 512 threads.
//   - attention: warp w = (row r = w&3, head hd = w>>2) — all 16 warps busy
//   - y = h + o@Wo : threads 0..255, thread=(r,c)
//   - a/b = y@W1 halves: thread=(c, row-pair): 256 cols x 2, 2 rows each
//     -> W1 L2 traffic: 256 blocks x 128KB = 32MB (4x cut vs per-row)
// ---------------------------------------------------------------------------
__global__ void k2_attn_ff(const float* __restrict__ Wo,
                           const float* __restrict__ W1,
                           const float* __restrict__ b1) {
    __shared__ float osh[K2R][Dd];
    __shared__ float ysh[K2R][Dd];
    const int t = threadIdx.x;
    const int warp = t >> 5, lane = t & 31;
    const int row0 = blockIdx.x * K2R;
    const int b = row0 >> 9, n0 = row0 & (Nn - 1);

    // ---- attention: warp = (r, hd) ----
    {
        const int r = warp & 3;
        const int hd = warp >> 2;
        const int i = n0 + r;
        const int cnt = g_cnt[i];
        const int* js = g_js + i * MAXD;
        const int nch = (cnt + 31) >> 5;   // <= 3

        const float* qrow = g_q + ((b * Hh + hd) * Nn + i) * DhD;
        float qr[DhD];
#pragma unroll
        for (int d = 0; d < DhD; d++) qr[d] = __ldg(qrow + d);

        const float* kbase = g_k + (b * Hh + hd) * Nn * DhD;
        const float* vbase = g_v + (b * Hh + hd) * Nn * DhD;

        float sc[3];
        int jj[3];
        float m = -3.0e38f;
#pragma unroll
        for (int c = 0; c < 3; c++) {
            sc[c] = -3.0e38f; jj[c] = 0;
            if (c < nch) {
                const int e = c * 32 + lane;
                if (e < cnt) {
                    const int j = js[e];
                    jj[c] = j;
                    const float* kr = kbase + j * DhD;
                    float dot = 0.f;
#pragma unroll
                    for (int d = 0; d < DhD; d++) dot += qr[d] * kr[d];
                    sc[c] = dot * 0.25f;
                }
                m = fmaxf(m, sc[c]);
            }
        }
#pragma unroll
        for (int o = 16; o > 0; o >>= 1)
            m = fmaxf(m, __shfl_xor_sync(0xffffffffu, m, o));

        float sum = 0.f;
#pragma unroll
        for (int c = 0; c < 3; c++) {
            sc[c] = expf(sc[c] - m);
            sum += sc[c];
        }
#pragma unroll
        for (int o = 16; o > 0; o >>= 1)
            sum += __shfl_xor_sync(0xffffffffu, sum, o);

        float ov[DhD];
#pragma unroll
        for (int d = 0; d < DhD; d++) ov[d] = 0.f;
#pragma unroll
        for (int c = 0; c < 3; c++) {
            if (c < nch && sc[c] > 0.f) {
                const float* vr = vbase + jj[c] * DhD;
                const float e = sc[c];
#pragma unroll
                for (int d = 0; d < DhD; d++) ov[d] += e * vr[d];
            }
        }
#pragma unroll
        for (int d = 0; d < DhD; d++) {
#pragma unroll
            for (int o = 16; o > 0; o >>= 1)
                ov[d] += __shfl_xor_sync(0xffffffffu, ov[d], o);
        }
        if (lane == 0) {
            const float inv = 1.f / sum;
#pragma unroll
            for (int d = 0; d < DhD; d++) osh[r][hd * DhD + d] = ov[d] * inv;
        }
    }
    __syncthreads();

    // ---- y = h + o @ Wo : threads 0..255, thread=(r,c) ----
    if (t < K2R * Dd) {
        const int r = t >> 6, c = t & 63;
        float acc = g_h[(row0 + r) * Dd + c];
#pragma unroll 8
        for (int e = 0; e < Dd; e++)
            acc += osh[r][e] * __ldg(Wo + e * Dd + c);
        ysh[r][c] = acc;
    }
    __syncthreads();

    // ---- a/b: thread=(c, row-pair). 512 threads: c = t&255, rh = t>>8 ----
    {
        const int c = t & 255;
        const int rh = t >> 8;              // 0 or 1 -> rows rh*2, rh*2+1
        const int rA = rh * 2, rB = rh * 2 + 1;
        const float bias = __ldg(b1 + c);
        float faA = 0.f, faB = 0.f, fbA = 0.f, fbB = 0.f;
#pragma unroll 8
        for (int d = 0; d < Dd; d++) {
            const float wa = __ldg(W1 + d * HIDD + c);
            const float wb = __ldg(W1 + (Dd + d) * HIDD + c);
            const float yA = ysh[rA][d], yB = ysh[rB][d];
            faA += yA * wa; faB += yB * wa;
            fbA += yA * wb; fbB += yB * wb;
        }
        g_a [(row0 + rA) * HIDD + c] = faA + bias;
        g_a [(row0 + rB) * HIDD + c] = faB + bias;
        g_bb[(row0 + rA) * HIDD + c] = fbA;
        g_bb[(row0 + rB) * HIDD + c] = fbB;
    }
}

// ---------------------------------------------------------------------------
// K3: sparse scatter only. grid = B*N blocks of 128.
// ---------------------------------------------------------------------------
__global__ void k3_out(const float* __restrict__ W2,
                       const float* __restrict__ b2,
                       float* __restrict__ out) {
    const int row = blockIdx.x;
    const int b = row >> 9, i = row & (Nn - 1);
    const int warp = threadIdx.x >> 5;
    const int lane = threadIdx.x & 31;

    const int cnt = g_cnt[i];
    const int* js = g_js + i * MAXD;
    const int h0 = lane * 8;

    const float4* ap = (const float4*)(g_a + row * HIDD + h0);
    const float4 a0 = ap[0], a1 = ap[1];
    float4 w[8];
#pragma unroll
    for (int k = 0; k < 8; k++) w[k] = __ldg((const float4*)W2 + h0 + k);
    const float b20 = __ldg(b2 + 0), b21 = __ldg(b2 + 1);
    const float b22 = __ldg(b2 + 2), b23 = __ldg(b2 + 3);

    for (int e = warp; e < cnt; e += 4) {
        const int j = js[e];
        const float4* bp = (const float4*)(g_bb + ((size_t)(b * Nn + j)) * HIDD + h0);
        const float4 bv0 = bp[0], bv1 = bp[1];

        float acc0 = 0.f, acc1 = 0.f, acc2 = 0.f, acc3 = 0.f;
        float t;
#define RELU_FMA(AV, BV, WK) \
        t = fmaxf((AV) + (BV), 0.f); \
        acc0 += t * (WK).x; acc1 += t * (WK).y; acc2 += t * (WK).z; acc3 += t * (WK).w;
        RELU_FMA(a0.x, bv0.x, w[0]);
        RELU_FMA(a0.y, bv0.y, w[1]);
        RELU_FMA(a0.z, bv0.z, w[2]);
        RELU_FMA(a0.w, bv0.w, w[3]);
        RELU_FMA(a1.x, bv1.x, w[4]);
        RELU_FMA(a1.y, bv1.y, w[5]);
        RELU_FMA(a1.z, bv1.z, w[6]);
        RELU_FMA(a1.w, bv1.w, w[7]);
#undef RELU_FMA

#pragma unroll
        for (int o = 16; o > 0; o >>= 1) {
            acc0 += __shfl_xor_sync(0xffffffffu, acc0, o);
            acc1 += __shfl_xor_sync(0xffffffffu, acc1, o);
            acc2 += __shfl_xor_sync(0xffffffffu, acc2, o);
            acc3 += __shfl_xor_sync(0xffffffffu, acc3, o);
        }
        if (lane == 0) {
            out[(((size_t)(b * Cc + 0) * Nn + i) * Nn) + j] = acc0 + b20;
            out[(((size_t)(b * Cc + 1) * Nn + i) * Nn) + j] = acc1 + b21;
            out[(((size_t)(b * Cc + 2) * Nn + i) * Nn) + j] = acc2 + b22;
            out[(((size_t)(b * Cc + 3) * Nn + i) * Nn) + j] = acc3 + b23;
        }
    }
}

// ---------------------------------------------------------------------------
extern "C" void kernel_launch(void* const* d_in, const int* in_sizes, int n_in,
                              void* d_out, int out_size) {
    const float* x     = (const float*)d_in[0];
    const float* adj   = (const float*)d_in[1];
    const float* W_emb = (const float*)d_in[2];
    const float* Wq    = (const float*)d_in[3];
    const float* Wk    = (const float*)d_in[4];
    const float* Wv    = (const float*)d_in[5];
    const float* Wo    = (const float*)d_in[6];
    const float* W1    = (const float*)d_in[7];
    const float* b1    = (const float*)d_in[8];
    const float* W2    = (const float*)d_in[9];
    const float* b2    = (const float*)d_in[10];
    float* out = (float*)d_out;

    k1_embed_qkv<<<Bb * Nn, 256>>>(x, adj, W_emb, Wq, Wk, Wv, out);
    k2_attn_ff<<<(Bb * Nn) / K2R, 512>>>(Wo, W1, b1);
    k3_out<<<Bb * Nn, 128>>>(W2, b2, out);
}